// round 3
// baseline (speedup 1.0000x reference)
#include <cuda_runtime.h>
#include <cstdint>

// POLLU RHS, persistent-CTA version.
// Input  conc: [20, B] species-major -> coalesced scalar LDG
// Output dy  : [B, 20] batch-major   -> double-buffered smem tiles drained by
//              1-D TMA bulk stores (cp.async.bulk), never blocking the mainloop.
//
// Pipeline per CTA (grid-stride over tiles of 256 columns):
//   compute -> wait_group 1 (buffer from 2 tiles ago drained) -> sync ->
//   STS (conflict-free 5x STS.128) -> fence+sync -> issue bulk store (no wait)

#define TILE 256
#define GRID 608   // ~4 CTAs/SM on 152 SMs; grid-stride handles any machine

__global__ __launch_bounds__(TILE)
void pollu_kernel(const float* __restrict__ conc,
                  const float* __restrict__ k,
                  float* __restrict__ out,
                  int B)
{
    __shared__ __align__(16) float s_dy[2][TILE * 20];

    const int tid = threadIdx.x;
    const int num_tiles = (B + TILE - 1) / TILE;

    int p = 0;
    for (int tile = blockIdx.x; tile < num_tiles; tile += GRID, p ^= 1) {
        const int b0 = tile * TILE;
        const int b  = b0 + tid;
        const int n_valid = min(TILE, B - b0);

        float d0=0,d1=0,d2=0,d3=0,d4=0,d5=0,d6=0,d7=0,d8=0,d9=0;
        float d10=0,d11=0,d12=0,d13=0,d14=0,d15=0,d16=0,d17=0,d18=0,d19=0;

        if (b < B) {
            // ---- coalesced loads: 20 species rows, stride B ----
            float C0  = __ldg(&conc[ 0*B + b]);
            float C1  = __ldg(&conc[ 1*B + b]);
            float C2  = __ldg(&conc[ 2*B + b]);
            float C3  = __ldg(&conc[ 3*B + b]);
            float C4  = __ldg(&conc[ 4*B + b]);
            float C5  = __ldg(&conc[ 5*B + b]);
            float C6  = __ldg(&conc[ 6*B + b]);
            float C8  = __ldg(&conc[ 8*B + b]);
            float C9  = __ldg(&conc[ 9*B + b]);
            float C10 = __ldg(&conc[10*B + b]);
            float C12 = __ldg(&conc[12*B + b]);
            float C13 = __ldg(&conc[13*B + b]);
            float C15 = __ldg(&conc[15*B + b]);
            float C16 = __ldg(&conc[16*B + b]);
            float C18 = __ldg(&conc[18*B + b]);
            float C19 = __ldg(&conc[19*B + b]);

            // ---- 25 fluxes (k loads are L1 hits) ----
            float r1  = __ldg(&k[ 0]) * C0;
            float r2  = __ldg(&k[ 1]) * C1  * C3;
            float r3  = __ldg(&k[ 2]) * C4  * C1;
            float r4  = __ldg(&k[ 3]) * C6;
            float r5  = __ldg(&k[ 4]) * C6;
            float r6  = __ldg(&k[ 5]) * C6  * C5;
            float r7  = __ldg(&k[ 6]) * C8;
            float r8  = __ldg(&k[ 7]) * C8  * C5;
            float r9  = __ldg(&k[ 8]) * C10 * C1;
            float r10 = __ldg(&k[ 9]) * C10 * C0;
            float r11 = __ldg(&k[10]) * C12;
            float r12 = __ldg(&k[11]) * C9  * C1;
            float r13 = __ldg(&k[12]) * C13;
            float r14 = __ldg(&k[13]) * C0  * C5;
            float r15 = __ldg(&k[14]) * C2;
            float r16 = __ldg(&k[15]) * C3;
            float r17 = __ldg(&k[16]) * C3;
            float r18 = __ldg(&k[17]) * C15;
            float r19 = __ldg(&k[18]) * C15;
            float r20 = __ldg(&k[19]) * C16 * C5;
            float r21 = __ldg(&k[20]) * C18;
            float r22 = __ldg(&k[21]) * C18;
            float r23 = __ldg(&k[22]) * C0  * C3;
            float r24 = __ldg(&k[23]) * C18 * C0;
            float r25 = __ldg(&k[24]) * C19;

            // ---- stoichiometry ----
            d0  = -r1 - r10 - r14 - r23 - r24 + r2 + r3 + r9 + r11 + r12 + r22 + r25;
            d1  = -r2 - r3 - r9 - r12 + r1 + r21;
            d2  = -r15 + r1 + r17 + r19 + r22;
            d3  = -r2 - r16 - r17 - r23 + r15;
            d4  = -r3 + 2.0f*r4 + r6 + r7 + r13 + r20;
            d5  = -r6 - r8 - r14 - r20 + r3 + 2.0f*r18;
            d6  = -r4 - r5 - r6 + r13;
            d7  =  r4 + r5 + r6 + r7;
            d8  = -r7 - r8;
            d9  = -r12 + r7 + r9;
            d10 = -r9 - r10 + r8 + r11;
            d11 =  r9;
            d12 = -r11 + r10;
            d13 = -r13 + r12;
            d14 =  r14;
            d15 = -r18 - r19 + r16;
            d16 = -r20;
            d17 =  r20;
            d18 = -r21 - r22 - r24 + r23 + r25;
            d19 = -r25 + r24;
        }

        // ---- ensure the bulk store issued 2 iterations ago (same buffer)
        //      has drained before overwriting; at most 1 group stays in flight
        if (tid == 0) {
            asm volatile("cp.async.bulk.wait_group 1;" ::: "memory");
        }
        __syncthreads();

        if (b < B) {
            // 5x STS.128, conflict-free in unpadded [TILE][20] layout:
            // 16B-chunk index = 5*tid + j; per 8-lane phase the banks
            // {0,20,8,28,16,4,24,12} are disjoint across all 32 banks.
            float4* srow = reinterpret_cast<float4*>(&s_dy[p][tid * 20]);
            srow[0] = make_float4(d0,  d1,  d2,  d3);
            srow[1] = make_float4(d4,  d5,  d6,  d7);
            srow[2] = make_float4(d8,  d9,  d10, d11);
            srow[3] = make_float4(d12, d13, d14, d15);
            srow[4] = make_float4(d16, d17, d18, d19);
        }
        __syncthreads();

        // ---- issue the bulk store; do NOT wait (drains in background) ----
        if (tid == 0) {
            asm volatile("fence.proxy.async.shared::cta;" ::: "memory");

            uint32_t smem_addr;
            asm("{ .reg .u64 t; cvta.to.shared.u64 t, %1; cvt.u32.u64 %0, t; }"
                : "=r"(smem_addr) : "l"(&s_dy[p][0]));

            float* gdst = out + (long long)b0 * 20;
            unsigned bytes = (unsigned)(n_valid * 20 * sizeof(float)); // mult of 16

            asm volatile(
                "cp.async.bulk.global.shared::cta.bulk_group [%0], [%1], %2;"
                :: "l"(gdst), "r"(smem_addr), "r"(bytes)
                : "memory");
            asm volatile("cp.async.bulk.commit_group;" ::: "memory");
        }
    }

    // drain all outstanding stores before CTA exit (smem deallocation)
    if (tid == 0) {
        asm volatile("cp.async.bulk.wait_group 0;" ::: "memory");
    }
}

extern "C" void kernel_launch(void* const* d_in, const int* in_sizes, int n_in,
                              void* d_out, int out_size)
{
    // inputs per metadata order: t [1], conc_in [20*B], k [25]
    const float* conc = (const float*)d_in[1];
    const float* k    = (const float*)d_in[2];
    float* out        = (float*)d_out;
    const int B = in_sizes[1] / 20;

    const int num_tiles = (B + TILE - 1) / TILE;
    const int grid = num_tiles < GRID ? num_tiles : GRID;
    pollu_kernel<<<grid, TILE>>>(conc, k, out, B);
}

// round 4
// speedup vs baseline: 1.0966x; 1.0966x over previous
#include <cuda_runtime.h>
#include <cstdint>

// POLLU RHS: dy[b][s] = sum_r S[s][r]*k[r]*C[a_r][b]*C[b_r][b]
// Input  conc: [20, B] species-major -> coalesced scalar LDG
// Output dy  : [B, 20] batch-major   -> per-WARP smem staging + per-warp 1-D
//              TMA bulk store (cp.async.bulk). NO block-wide barriers:
//              each warp computes, stages its 32x20 span (2560B contiguous),
//              and drains it independently.

#define TILE 256   // 8 warps/block, 1 column/thread

__global__ __launch_bounds__(TILE)
void pollu_kernel(const float* __restrict__ conc,
                  const float* __restrict__ k,
                  float* __restrict__ out,
                  int B)
{
    __shared__ __align__(16) float s_dy[TILE * 20];   // 20 KB, warp w owns [w*640 .. w*640+640)

    const int tid  = threadIdx.x;
    const int wid  = tid >> 5;
    const int lane = tid & 31;
    const int b0   = blockIdx.x * TILE;
    const int b    = b0 + tid;

    const int warp_b0    = b0 + wid * 32;            // first column this warp owns
    const int warp_valid = min(32, B - warp_b0);     // may be <=0 for tail warps

    if (b < B) {
        // ---- coalesced loads: 20 species rows, stride B ----
        float C0  = __ldg(&conc[ 0*B + b]);
        float C1  = __ldg(&conc[ 1*B + b]);
        float C2  = __ldg(&conc[ 2*B + b]);
        float C3  = __ldg(&conc[ 3*B + b]);
        float C4  = __ldg(&conc[ 4*B + b]);
        float C5  = __ldg(&conc[ 5*B + b]);
        float C6  = __ldg(&conc[ 6*B + b]);
        float C8  = __ldg(&conc[ 8*B + b]);
        float C9  = __ldg(&conc[ 9*B + b]);
        float C10 = __ldg(&conc[10*B + b]);
        float C12 = __ldg(&conc[12*B + b]);
        float C13 = __ldg(&conc[13*B + b]);
        float C15 = __ldg(&conc[15*B + b]);
        float C16 = __ldg(&conc[16*B + b]);
        float C18 = __ldg(&conc[18*B + b]);
        float C19 = __ldg(&conc[19*B + b]);

        // ---- 25 fluxes (k loads broadcast, L1-resident) ----
        float r1  = __ldg(&k[ 0]) * C0;
        float r2  = __ldg(&k[ 1]) * C1  * C3;
        float r3  = __ldg(&k[ 2]) * C4  * C1;
        float r4  = __ldg(&k[ 3]) * C6;
        float r5  = __ldg(&k[ 4]) * C6;
        float r6  = __ldg(&k[ 5]) * C6  * C5;
        float r7  = __ldg(&k[ 6]) * C8;
        float r8  = __ldg(&k[ 7]) * C8  * C5;
        float r9  = __ldg(&k[ 8]) * C10 * C1;
        float r10 = __ldg(&k[ 9]) * C10 * C0;
        float r11 = __ldg(&k[10]) * C12;
        float r12 = __ldg(&k[11]) * C9  * C1;
        float r13 = __ldg(&k[12]) * C13;
        float r14 = __ldg(&k[13]) * C0  * C5;
        float r15 = __ldg(&k[14]) * C2;
        float r16 = __ldg(&k[15]) * C3;
        float r17 = __ldg(&k[16]) * C3;
        float r18 = __ldg(&k[17]) * C15;
        float r19 = __ldg(&k[18]) * C15;
        float r20 = __ldg(&k[19]) * C16 * C5;
        float r21 = __ldg(&k[20]) * C18;
        float r22 = __ldg(&k[21]) * C18;
        float r23 = __ldg(&k[22]) * C0  * C3;
        float r24 = __ldg(&k[23]) * C18 * C0;
        float r25 = __ldg(&k[24]) * C19;

        // ---- stoichiometry ----
        float d0  = -r1 - r10 - r14 - r23 - r24 + r2 + r3 + r9 + r11 + r12 + r22 + r25;
        float d1  = -r2 - r3 - r9 - r12 + r1 + r21;
        float d2  = -r15 + r1 + r17 + r19 + r22;
        float d3  = -r2 - r16 - r17 - r23 + r15;
        float d4  = -r3 + 2.0f*r4 + r6 + r7 + r13 + r20;
        float d5  = -r6 - r8 - r14 - r20 + r3 + 2.0f*r18;
        float d6  = -r4 - r5 - r6 + r13;
        float d7  =  r4 + r5 + r6 + r7;
        float d8  = -r7 - r8;
        float d9  = -r12 + r7 + r9;
        float d10 = -r9 - r10 + r8 + r11;
        float d11 =  r9;
        float d12 = -r11 + r10;
        float d13 = -r13 + r12;
        float d14 =  r14;
        float d15 = -r18 - r19 + r16;
        float d16 = -r20;
        float d17 =  r20;
        float d18 = -r21 - r22 - r24 + r23 + r25;
        float d19 = -r25 + r24;

        // ---- 5x STS.128, conflict-free in unpadded [TILE][20]:
        // 16B-chunk index = 5*tid + j; each 8-lane phase hits 8 disjoint
        // bank-groups {0,20,8,28,16,4,24,12} mod 32.
        float4* srow = reinterpret_cast<float4*>(&s_dy[tid * 20]);
        srow[0] = make_float4(d0,  d1,  d2,  d3);
        srow[1] = make_float4(d4,  d5,  d6,  d7);
        srow[2] = make_float4(d8,  d9,  d10, d11);
        srow[3] = make_float4(d12, d13, d14, d15);
        srow[4] = make_float4(d16, d17, d18, d19);
    }

    // ---- per-warp drain: no block barrier anywhere ----
    __syncwarp();
    if (warp_valid > 0) {
        // order this warp's generic-proxy smem writes before the async-proxy read
        asm volatile("fence.proxy.async.shared::cta;" ::: "memory");
        if (lane == 0) {
            uint32_t smem_addr;
            asm("{ .reg .u64 t; cvta.to.shared.u64 t, %1; cvt.u32.u64 %0, t; }"
                : "=r"(smem_addr) : "l"(&s_dy[wid * 32 * 20]));

            float*   gdst  = out + (long long)warp_b0 * 20;        // 2560B-aligned span
            unsigned bytes = (unsigned)(warp_valid * 20 * sizeof(float)); // mult of 16

            asm volatile(
                "cp.async.bulk.global.shared::cta.bulk_group [%0], [%1], %2;"
                :: "l"(gdst), "r"(smem_addr), "r"(bytes)
                : "memory");
            asm volatile("cp.async.bulk.commit_group;" ::: "memory");
            asm volatile("cp.async.bulk.wait_group 0;" ::: "memory");
        }
    }
}

extern "C" void kernel_launch(void* const* d_in, const int* in_sizes, int n_in,
                              void* d_out, int out_size)
{
    // inputs per metadata order: t [1], conc_in [20*B], k [25]
    const float* conc = (const float*)d_in[1];
    const float* k    = (const float*)d_in[2];
    float* out        = (float*)d_out;
    const int B = in_sizes[1] / 20;

    const int grid = (B + TILE - 1) / TILE;
    pollu_kernel<<<grid, TILE>>>(conc, k, out, B);
}